// round 2
// baseline (speedup 1.0000x reference)
#include <cuda_runtime.h>
#include <math.h>

#define DD 128
#define HH 4
#define NWARPS 8
#define NTHREADS 256
#define CHUNK 512

// Scratch for raw scores / exp values, [N, H] layout. N=500000 in this problem;
// sized with margin. Static __device__ array (no allocation per harness rules).
__device__ float g_scores[600000 * HH];

__global__ __launch_bounds__(NTHREADS)
void mhap_kernel(const float* __restrict__ x,
                 const int*   __restrict__ ids32,  // raw index buffer; may really be int64
                 const float* __restrict__ W,      // [H, D]
                 const float* __restrict__ bias,   // [H]
                 const float* __restrict__ temp,   // scalar
                 float* __restrict__ pooled,       // [B, D]
                 float* __restrict__ attn,         // [H, N]
                 int N)
{
    __shared__ int   s_lo, s_hi;
    __shared__ float s_red[NWARPS][HH];
    __shared__ float s_m[HH];
    __shared__ float s_inv[HH];
    __shared__ float s_w[CHUNK];

    const int tid  = threadIdx.x;
    const int lane = tid & 31;
    const int warp = tid >> 5;
    const int b    = blockIdx.x;

    // ---- segment bounds via binary search (indices sorted) ----
    if (tid == 0) {
        // int64-vs-int32 detection: if the buffer is int64, int32-element N-1 is
        // the high word of element (N-1)/2 (N-1 odd for even N) == 0. If it is
        // real int32 data, the last sorted id ~ B-1 > 0. Deterministic.
        const int stride = (ids32[N - 1] == 0) ? 2 : 1;
        int lo = 0, hi = N;
        while (lo < hi) { int mid = (lo + hi) >> 1; if (ids32[(size_t)mid * stride] <  b) lo = mid + 1; else hi = mid; }
        s_lo = lo;
        int lo2 = lo, hi2 = N;
        while (lo2 < hi2) { int mid = (lo2 + hi2) >> 1; if (ids32[(size_t)mid * stride] <= b) lo2 = mid + 1; else hi2 = mid; }
        s_hi = lo2;
    }
    __syncthreads();
    const int lo  = s_lo;
    const int hi  = s_hi;
    const int cnt = hi - lo;

    if (cnt == 0) {
        // empty segment: pooled row is zeros (d_out is poisoned, must write)
        if (tid < DD) pooled[(size_t)b * DD + tid] = 0.0f;
        return;
    }

    const float invT = 1.0f / temp[0];

    // per-lane slice of W: lane covers x[4*lane .. 4*lane+3]
    float wreg[HH][4];
    float bb[HH];
    #pragma unroll
    for (int h = 0; h < HH; h++) {
        const float4 wv = *reinterpret_cast<const float4*>(W + h * DD + lane * 4);
        wreg[h][0] = wv.x; wreg[h][1] = wv.y; wreg[h][2] = wv.z; wreg[h][3] = wv.w;
        bb[h] = bias[h];
    }

    // ---- Pass 1: scores + per-head segment max. warp per node. ----
    float lmax[HH];
    #pragma unroll
    for (int h = 0; h < HH; h++) lmax[h] = -INFINITY;

    for (int n = lo + warp; n < hi; n += NWARPS) {
        const float4 xv = *reinterpret_cast<const float4*>(x + (size_t)n * DD + lane * 4);
        float s[HH];
        #pragma unroll
        for (int h = 0; h < HH; h++)
            s[h] = xv.x * wreg[h][0] + xv.y * wreg[h][1] + xv.z * wreg[h][2] + xv.w * wreg[h][3];
        #pragma unroll
        for (int off = 16; off > 0; off >>= 1) {
            #pragma unroll
            for (int h = 0; h < HH; h++)
                s[h] += __shfl_xor_sync(0xffffffffu, s[h], off);
        }
        #pragma unroll
        for (int h = 0; h < HH; h++) {
            s[h] = (s[h] + bb[h]) * invT;
            lmax[h] = fmaxf(lmax[h], s[h]);
        }
        if (lane < HH) g_scores[(size_t)n * HH + lane] = s[lane];
    }
    if (lane == 0) {
        #pragma unroll
        for (int h = 0; h < HH; h++) s_red[warp][h] = lmax[h];
    }
    __syncthreads();
    if (tid < HH) {
        float m = -INFINITY;
        #pragma unroll
        for (int w = 0; w < NWARPS; w++) m = fmaxf(m, s_red[w][tid]);
        s_m[tid] = m;
    }
    __syncthreads();

    // ---- Pass 2: exp + per-head segment sum. thread per (node,head). ----
    {
        const int   total = cnt * HH;
        const int   myh   = tid & 3;                 // (lo*4 + i) & 3 == tid & 3
        const float m     = s_m[myh];
        float lsum = 0.0f;
        const size_t base = (size_t)lo * HH;
        for (int i = tid; i < total; i += NTHREADS) {
            const float e = __expf(g_scores[base + i] - m);
            g_scores[base + i] = e;
            lsum += e;
        }
        // reduce lanes sharing the same h (lane & 3)
        lsum += __shfl_xor_sync(0xffffffffu, lsum, 16);
        lsum += __shfl_xor_sync(0xffffffffu, lsum, 8);
        lsum += __shfl_xor_sync(0xffffffffu, lsum, 4);
        if (lane < HH) s_red[warp][lane] = lsum;
    }
    __syncthreads();
    if (tid < HH) {
        float s = 0.0f;
        #pragma unroll
        for (int w = 0; w < NWARPS; w++) s += s_red[w][tid];
        s_inv[tid] = 1.0f / s;
    }
    __syncthreads();

    // ---- Pass 3 (chunked): normalize -> attn out; node weights -> pooling ----
    float acc0 = 0.0f, acc1 = 0.0f;
    const int d    = tid & 127;
    const int half = tid >> 7;   // 0 or 1: split nodes even/odd

    for (int cs = lo; cs < hi; cs += CHUNK) {
        const int cn   = (hi - cs < CHUNK) ? (hi - cs) : CHUNK;
        const int tot4 = cn * HH;

        // step A: attn = e * inv; per-node weight = mean over heads
        for (int i0 = 0; i0 < tot4; i0 += NTHREADS) {
            const int  i     = i0 + tid;
            const bool valid = (i < tot4);
            float a = 0.0f;
            const int nloc = i >> 2;
            const int h    = i & 3;
            if (valid) {
                a = g_scores[(size_t)cs * HH + i] * s_inv[h];
                attn[(size_t)h * N + (cs + nloc)] = a;
            }
            // sum 4 consecutive lanes (one node's 4 heads)
            a += __shfl_down_sync(0xffffffffu, a, 2);
            a += __shfl_down_sync(0xffffffffu, a, 1);
            if (valid && h == 0) s_w[nloc] = a * 0.25f;
        }
        __syncthreads();

        // step B: pooled accumulation; column d, nodes split by half, unroll 2
        {
            int j = half;
            for (; j + 2 < cn; j += 4) {
                acc0 += s_w[j]     * x[(size_t)(cs + j)     * DD + d];
                acc1 += s_w[j + 2] * x[(size_t)(cs + j + 2) * DD + d];
            }
            for (; j < cn; j += 2)
                acc0 += s_w[j] * x[(size_t)(cs + j) * DD + d];
        }
        __syncthreads();
    }

    // combine the two node-halves per column
    s_w[tid] = acc0 + acc1;
    __syncthreads();
    if (tid < DD)
        pooled[(size_t)b * DD + tid] = s_w[tid] + s_w[tid + 128];
}

extern "C" void kernel_launch(void* const* d_in, const int* in_sizes, int n_in,
                              void* d_out, int out_size)
{
    const float* x    = (const float*)d_in[0];
    const int*   ids  = (const int*)  d_in[1];
    const float* W    = (const float*)d_in[2];
    const float* bias = (const float*)d_in[3];
    const float* temp = (const float*)d_in[4];

    const int N = in_sizes[0] / DD;          // x is [N, 128]
    const int B = (out_size - HH * N) / DD;  // out = [B*D pooled | H*N attn]

    float* pooled = (float*)d_out;
    float* attn   = (float*)d_out + (size_t)B * DD;

    mhap_kernel<<<B, NTHREADS>>>(x, ids, W, bias, temp, pooled, attn, N);
    (void)n_in;
}

// round 4
// speedup vs baseline: 1.5048x; 1.5048x over previous
#include <cuda_runtime.h>
#include <math.h>

#define DD 128
#define HH 4
#define NWARPS 8
#define NTHREADS 256
#define SMAX 88          // nodes cached in smem per chunk (45KB)

// Segment offsets: g_off[b] = first node index of segment b; g_off[B] = N.
__device__ int g_off[8320];
// Fallback scratch for rare segments with cnt > SMAX (scores, [N,H]).
__device__ float g_scores[600000 * HH];

// ---------------------------------------------------------------------------
// Kernel 0: build segment offsets from sorted ids (int32 or int64 low words).
// ---------------------------------------------------------------------------
__global__ void seg_offsets_kernel(const int* __restrict__ ids32, int N, int B)
{
    const int stride = (ids32[N - 1] == 0) ? 2 : 1;   // int64 buffers: high word of last elem == 0
    for (int i = blockIdx.x * blockDim.x + threadIdx.x; i < N;
         i += gridDim.x * blockDim.x) {
        const int cur  = ids32[(size_t)i * stride];
        const int prev = (i == 0) ? -1 : ids32[(size_t)(i - 1) * stride];
        for (int b = prev + 1; b <= cur; b++) g_off[b] = i;
        if (i == N - 1)
            for (int b = cur + 1; b <= B; b++) g_off[b] = N;
    }
}

// ---------------------------------------------------------------------------
// Kernel 1: one CTA per segment. x staged in smem; softmax + pooling fused.
// ---------------------------------------------------------------------------
__global__ __launch_bounds__(NTHREADS)
void mhap_kernel(const float* __restrict__ x,
                 const float* __restrict__ W,      // [H, D]
                 const float* __restrict__ bias,   // [H]
                 const float* __restrict__ temp,   // scalar
                 float* __restrict__ pooled,       // [B, D]
                 float* __restrict__ attn,         // [H, N]
                 int N)
{
    __shared__ __align__(16) float sx[SMAX * DD];   // 45KB: chunk of x rows
    __shared__ __align__(16) float ssc[SMAX * HH];  // scores / exp values (fits path)
    __shared__ float s_w[SMAX];                     // per-node pooling weight
    __shared__ float s_red[NWARPS][HH];
    __shared__ float s_m[HH];
    __shared__ float s_inv[HH];

    const int tid  = threadIdx.x;
    const int lane = tid & 31;
    const int warp = tid >> 5;
    const int b    = blockIdx.x;

    const int lo  = g_off[b];
    const int hi  = g_off[b + 1];
    const int cnt = hi - lo;

    if (cnt == 0) {
        if (tid < DD) pooled[(size_t)b * DD + tid] = 0.0f;   // d_out poisoned
        return;
    }

    const bool  fits = (cnt <= SMAX);
    const float invT = 1.0f / temp[0];

    // W slice per lane: covers x[4*lane .. 4*lane+3]
    float wreg[HH][4];
    float bb[HH];
    #pragma unroll
    for (int h = 0; h < HH; h++) {
        const float4 wv = *reinterpret_cast<const float4*>(W + h * DD + lane * 4);
        wreg[h][0] = wv.x; wreg[h][1] = wv.y; wreg[h][2] = wv.z; wreg[h][3] = wv.w;
        bb[h] = bias[h];
    }

    float4*       sx4 = reinterpret_cast<float4*>(sx);
    const float4* x4  = reinterpret_cast<const float4*>(x);

    // ==== Phase A: per chunk: stage x -> smem (high-MLP flat copy), scores ====
    float lmax[HH];
    #pragma unroll
    for (int h = 0; h < HH; h++) lmax[h] = -INFINITY;

    for (int c = 0; c < cnt; c += SMAX) {
        const int cn = (cnt - c < SMAX) ? (cnt - c) : SMAX;

        // flat cooperative load: cn*32 independent float4s, fully coalesced
        const size_t gbase = (size_t)(lo + c) * (DD / 4);
        for (int i = tid; i < cn * (DD / 4); i += NTHREADS)
            sx4[i] = x4[gbase + i];
        __syncthreads();

        // warp per node from smem
        for (int n = warp; n < cn; n += NWARPS) {
            const float4 xv = sx4[n * (DD / 4) + lane];
            float s[HH];
            #pragma unroll
            for (int h = 0; h < HH; h++)
                s[h] = xv.x * wreg[h][0] + xv.y * wreg[h][1]
                     + xv.z * wreg[h][2] + xv.w * wreg[h][3];
            #pragma unroll
            for (int off = 16; off > 0; off >>= 1) {
                #pragma unroll
                for (int h = 0; h < HH; h++)
                    s[h] += __shfl_xor_sync(0xffffffffu, s[h], off);
            }
            #pragma unroll
            for (int h = 0; h < HH; h++) {
                s[h] = (s[h] + bb[h]) * invT;
                lmax[h] = fmaxf(lmax[h], s[h]);
            }
            if (lane < HH) {
                if (fits) ssc[n * HH + lane] = s[lane];
                else      g_scores[(size_t)(lo + c + n) * HH + lane] = s[lane];
            }
        }
        if (!fits) __syncthreads();   // before next chunk overwrites sx
    }

    if (lane == 0) {
        #pragma unroll
        for (int h = 0; h < HH; h++) s_red[warp][h] = lmax[h];
    }
    __syncthreads();
    if (tid < HH) {
        float m = -INFINITY;
        #pragma unroll
        for (int w = 0; w < NWARPS; w++) m = fmaxf(m, s_red[w][tid]);
        s_m[tid] = m;
    }
    __syncthreads();

    // ==== Phase B: exp + per-head sum -> 1/Z ====
    {
        const int   total = cnt * HH;
        const float m     = s_m[tid & 3];
        float lsum = 0.0f;
        if (fits) {
            for (int i = tid; i < total; i += NTHREADS) {
                const float e = __expf(ssc[i] - m);
                ssc[i] = e;
                lsum += e;
            }
        } else {
            const size_t base = (size_t)lo * HH;
            for (int i = tid; i < total; i += NTHREADS) {
                const float e = __expf(g_scores[base + i] - m);
                g_scores[base + i] = e;
                lsum += e;
            }
        }
        lsum += __shfl_xor_sync(0xffffffffu, lsum, 16);
        lsum += __shfl_xor_sync(0xffffffffu, lsum, 8);
        lsum += __shfl_xor_sync(0xffffffffu, lsum, 4);
        if (lane < HH) s_red[warp][lane] = lsum;
    }
    __syncthreads();
    if (tid < HH) {
        float s = 0.0f;
        #pragma unroll
        for (int w = 0; w < NWARPS; w++) s += s_red[w][tid];
        s_inv[tid] = 1.0f / s;
    }
    __syncthreads();

    const float i0 = s_inv[0], i1 = s_inv[1], i2 = s_inv[2], i3 = s_inv[3];

    // ==== Phase C: attn writes + node weights + pooling ====
    float acc0 = 0.0f, acc1 = 0.0f;
    const int d    = tid & 127;
    const int half = tid >> 7;

    for (int c = 0; c < cnt; c += SMAX) {
        const int cn = (cnt - c < SMAX) ? (cnt - c) : SMAX;
        const float* esrc = fits ? ssc : (g_scores + (size_t)(lo + c) * HH);
        const float4* e4  = reinterpret_cast<const float4*>(esrc);

        // per-node pooling weight: mean over normalized heads (one float4 LDS/LDG)
        for (int j = tid; j < cn; j += NTHREADS) {
            const float4 e = e4[j];
            s_w[j] = 0.25f * (e.x * i0 + e.y * i1 + e.z * i2 + e.w * i3);
        }
        // attn: per-head contiguous, fully coalesced writes
        #pragma unroll
        for (int h = 0; h < HH; h++) {
            const float ih = s_inv[h];
            float* dst = attn + (size_t)h * N + lo + c;
            for (int j = tid; j < cn; j += NTHREADS)
                dst[j] = esrc[j * HH + h] * ih;
        }
        __syncthreads();

        // pooled accumulation: column d, nodes split even/odd across halves
        if (fits) {
            int j = half;
            for (; j + 2 < cn; j += 4) {
                acc0 += s_w[j]     * sx[j       * DD + d];
                acc1 += s_w[j + 2] * sx[(j + 2) * DD + d];
            }
            for (; j < cn; j += 2)
                acc0 += s_w[j] * sx[j * DD + d];
        } else {
            const float* xrow = x + (size_t)(lo + c) * DD + d;
            int j = half;
            for (; j + 2 < cn; j += 4) {
                acc0 += s_w[j]     * xrow[(size_t)j       * DD];
                acc1 += s_w[j + 2] * xrow[(size_t)(j + 2) * DD];
            }
            for (; j < cn; j += 2)
                acc0 += s_w[j] * xrow[(size_t)j * DD];
        }
        __syncthreads();
    }

    // combine the two node-halves per column (reuse sx)
    sx[tid] = acc0 + acc1;
    __syncthreads();
    if (tid < DD)
        pooled[(size_t)b * DD + tid] = sx[tid] + sx[tid + DD];
}

extern "C" void kernel_launch(void* const* d_in, const int* in_sizes, int n_in,
                              void* d_out, int out_size)
{
    const float* x    = (const float*)d_in[0];
    const int*   ids  = (const int*)  d_in[1];
    const float* W    = (const float*)d_in[2];
    const float* bias = (const float*)d_in[3];
    const float* temp = (const float*)d_in[4];

    const int N = in_sizes[0] / DD;          // x is [N, 128]
    const int B = (out_size - HH * N) / DD;  // out = [B*D pooled | H*N attn]

    float* pooled = (float*)d_out;
    float* attn   = (float*)d_out + (size_t)B * DD;

    int blocks0 = (N + 255) / 256;
    if (blocks0 > 2048) blocks0 = 2048;
    seg_offsets_kernel<<<blocks0, 256>>>(ids, N, B);
    mhap_kernel<<<B, NTHREADS>>>(x, W, bias, temp, pooled, attn, N);
    (void)n_in;
}

// round 5
// speedup vs baseline: 1.6049x; 1.0665x over previous
#include <cuda_runtime.h>
#include <math.h>

#define DD 128
#define HH 4
#define NWARPS 8
#define NTHREADS 256
#define SMAX 80          // nodes cached in smem (fits path)
#define RS 132           // padded row stride in floats (bank-conflict-free)
#define RS4 33           // padded row stride in float4

// Segment offsets: g_off[b] = first node of segment b; g_off[B] = N.
__device__ int g_off[8320];
// Fallback scratch (scores, [N,H]) for rare segments with cnt > SMAX.
__device__ float g_scores[600000 * HH];

// ---------------------------------------------------------------------------
// Kernel 0: build segment offsets from sorted ids (int32 or int64 low words).
// ---------------------------------------------------------------------------
__global__ void seg_offsets_kernel(const int* __restrict__ ids32, int N, int B)
{
    const int stride = (ids32[N - 1] == 0) ? 2 : 1;   // int64: high word of last elem == 0
    for (int i = blockIdx.x * blockDim.x + threadIdx.x; i < N;
         i += gridDim.x * blockDim.x) {
        const int cur  = ids32[(size_t)i * stride];
        const int prev = (i == 0) ? -1 : ids32[(size_t)(i - 1) * stride];
        for (int bb = prev + 1; bb <= cur; bb++) g_off[bb] = i;
        if (i == N - 1)
            for (int bb = cur + 1; bb <= B; bb++) g_off[bb] = N;
    }
}

// ---------------------------------------------------------------------------
// Kernel 1: one CTA per segment.
// ---------------------------------------------------------------------------
__global__ __launch_bounds__(NTHREADS)
void mhap_kernel(const float* __restrict__ x,
                 const float* __restrict__ W,      // [H, D]
                 const float* __restrict__ bias,   // [H]
                 const float* __restrict__ temp,   // scalar
                 float* __restrict__ pooled,       // [B, D]
                 float* __restrict__ attn,         // [H, N]
                 int N)
{
    __shared__ __align__(16) float sx[SMAX * RS];      // 42.2KB padded x rows
    __shared__ __align__(16) float sw[HH * DD];        // 2KB W
    __shared__ __align__(16) float s_part[NWARPS * DD];// 4KB pooling partials
    __shared__ float s_w[SMAX];
    __shared__ float s_red[NWARPS][HH];
    __shared__ float s_m[HH];
    __shared__ float s_inv[HH];

    const int tid  = threadIdx.x;
    const int lane = tid & 31;
    const int warp = tid >> 5;
    const int b    = blockIdx.x;

    const int lo  = g_off[b];
    const int hi  = g_off[b + 1];
    const int cnt = hi - lo;

    if (cnt == 0) {
        if (tid < DD) pooled[(size_t)b * DD + tid] = 0.0f;   // d_out poisoned
        return;
    }

    const bool  fits = (cnt <= SMAX);
    const float invT = 1.0f / temp[0];

    float4*       sx4 = reinterpret_cast<float4*>(sx);
    const float4* sw4 = reinterpret_cast<const float4*>(sw);
    const float4* x4  = reinterpret_cast<const float4*>(x);

    // stage W (512 floats); sync is merged with the first x-staging barrier
    for (int i = tid; i < HH * DD; i += NTHREADS) sw[i] = W[i];

    float s0 = 0.f, s1 = 0.f, s2 = 0.f, s3 = 0.f;       // this thread's scores
    float m0 = -INFINITY, m1 = -INFINITY, m2 = -INFINITY, m3 = -INFINITY;

    // ==== Phase A: stage x, thread-per-node scoring ====
    if (fits) {
        for (int i = tid; i < cnt * 32; i += NTHREADS) {
            const int r = i >> 5, k = i & 31;
            sx4[r * RS4 + k] = x4[(size_t)(lo + r) * 32 + k];
        }
        __syncthreads();
        if (tid < cnt) {
            const float4* row = sx4 + tid * RS4;
            #pragma unroll 4
            for (int k = 0; k < 32; k++) {
                const float4 xv = row[k];
                const float4 w0 = sw4[k];
                const float4 w1 = sw4[32 + k];
                const float4 w2 = sw4[64 + k];
                const float4 w3 = sw4[96 + k];
                s0 += xv.x * w0.x + xv.y * w0.y + xv.z * w0.z + xv.w * w0.w;
                s1 += xv.x * w1.x + xv.y * w1.y + xv.z * w1.z + xv.w * w1.w;
                s2 += xv.x * w2.x + xv.y * w2.y + xv.z * w2.z + xv.w * w2.w;
                s3 += xv.x * w3.x + xv.y * w3.y + xv.z * w3.z + xv.w * w3.w;
            }
            s0 = (s0 + bias[0]) * invT;  s1 = (s1 + bias[1]) * invT;
            s2 = (s2 + bias[2]) * invT;  s3 = (s3 + bias[3]) * invT;
            m0 = s0; m1 = s1; m2 = s2; m3 = s3;
        }
    } else {
        for (int c = 0; c < cnt; c += SMAX) {
            const int cn = (cnt - c < SMAX) ? (cnt - c) : SMAX;
            for (int i = tid; i < cn * 32; i += NTHREADS) {
                const int r = i >> 5, k = i & 31;
                sx4[r * RS4 + k] = x4[(size_t)(lo + c + r) * 32 + k];
            }
            __syncthreads();
            if (tid < cn) {
                float a0 = 0.f, a1 = 0.f, a2 = 0.f, a3 = 0.f;
                const float4* row = sx4 + tid * RS4;
                #pragma unroll 4
                for (int k = 0; k < 32; k++) {
                    const float4 xv = row[k];
                    const float4 w0 = sw4[k];
                    const float4 w1 = sw4[32 + k];
                    const float4 w2 = sw4[64 + k];
                    const float4 w3 = sw4[96 + k];
                    a0 += xv.x * w0.x + xv.y * w0.y + xv.z * w0.z + xv.w * w0.w;
                    a1 += xv.x * w1.x + xv.y * w1.y + xv.z * w1.z + xv.w * w1.w;
                    a2 += xv.x * w2.x + xv.y * w2.y + xv.z * w2.z + xv.w * w2.w;
                    a3 += xv.x * w3.x + xv.y * w3.y + xv.z * w3.z + xv.w * w3.w;
                }
                a0 = (a0 + bias[0]) * invT;  a1 = (a1 + bias[1]) * invT;
                a2 = (a2 + bias[2]) * invT;  a3 = (a3 + bias[3]) * invT;
                m0 = fmaxf(m0, a0); m1 = fmaxf(m1, a1);
                m2 = fmaxf(m2, a2); m3 = fmaxf(m3, a3);
                float4* gs = reinterpret_cast<float4*>(g_scores) + (lo + c + tid);
                *gs = make_float4(a0, a1, a2, a3);
            }
            __syncthreads();   // before next chunk overwrites sx
        }
    }

    // ==== block max per head (once per warp, not per node) ====
    #pragma unroll
    for (int off = 16; off > 0; off >>= 1) {
        m0 = fmaxf(m0, __shfl_xor_sync(0xffffffffu, m0, off));
        m1 = fmaxf(m1, __shfl_xor_sync(0xffffffffu, m1, off));
        m2 = fmaxf(m2, __shfl_xor_sync(0xffffffffu, m2, off));
        m3 = fmaxf(m3, __shfl_xor_sync(0xffffffffu, m3, off));
    }
    if (lane == 0) {
        s_red[warp][0] = m0; s_red[warp][1] = m1;
        s_red[warp][2] = m2; s_red[warp][3] = m3;
    }
    __syncthreads();
    if (tid < HH) {
        float m = -INFINITY;
        #pragma unroll
        for (int w = 0; w < NWARPS; w++) m = fmaxf(m, s_red[w][tid]);
        s_m[tid] = m;
    }
    __syncthreads();

    // ==== Phase B: exp + per-head sum -> 1/Z ====
    float e0 = 0.f, e1 = 0.f, e2 = 0.f, e3 = 0.f;
    if (fits) {
        if (tid < cnt) {
            e0 = __expf(s0 - s_m[0]); e1 = __expf(s1 - s_m[1]);
            e2 = __expf(s2 - s_m[2]); e3 = __expf(s3 - s_m[3]);
        }
        float t0 = e0, t1 = e1, t2 = e2, t3 = e3;
        #pragma unroll
        for (int off = 16; off > 0; off >>= 1) {
            t0 += __shfl_xor_sync(0xffffffffu, t0, off);
            t1 += __shfl_xor_sync(0xffffffffu, t1, off);
            t2 += __shfl_xor_sync(0xffffffffu, t2, off);
            t3 += __shfl_xor_sync(0xffffffffu, t3, off);
        }
        if (lane == 0) {
            s_red[warp][0] = t0; s_red[warp][1] = t1;
            s_red[warp][2] = t2; s_red[warp][3] = t3;
        }
    } else {
        const float m    = s_m[tid & 3];
        const int   tot  = cnt * HH;
        const size_t base = (size_t)lo * HH;
        float lsum = 0.f;
        for (int i = tid; i < tot; i += NTHREADS) {
            const float e = __expf(g_scores[base + i] - m);
            g_scores[base + i] = e;
            lsum += e;
        }
        lsum += __shfl_xor_sync(0xffffffffu, lsum, 16);
        lsum += __shfl_xor_sync(0xffffffffu, lsum, 8);
        lsum += __shfl_xor_sync(0xffffffffu, lsum, 4);
        if (lane < HH) s_red[warp][lane] = lsum;
    }
    __syncthreads();
    if (tid < HH) {
        float s = 0.f;
        #pragma unroll
        for (int w = 0; w < NWARPS; w++) s += s_red[w][tid];
        s_inv[tid] = 1.0f / s;
    }
    __syncthreads();

    const float i0 = s_inv[0], i1 = s_inv[1], i2 = s_inv[2], i3 = s_inv[3];

    // ==== Phase C: attn writes + node weights + pooling ====
    float4 acc = make_float4(0.f, 0.f, 0.f, 0.f);

    if (fits) {
        if (tid < cnt) {
            const float a0 = e0 * i0, a1 = e1 * i1, a2 = e2 * i2, a3 = e3 * i3;
            attn[lo + tid]                  = a0;
            attn[(size_t)N + lo + tid]      = a1;
            attn[(size_t)2 * N + lo + tid]  = a2;
            attn[(size_t)3 * N + lo + tid]  = a3;
            s_w[tid] = 0.25f * (a0 + a1 + a2 + a3);
        }
        __syncthreads();
        for (int j = warp; j < cnt; j += NWARPS) {
            const float wj  = s_w[j];
            const float4 xv = sx4[j * RS4 + lane];
            acc.x += wj * xv.x; acc.y += wj * xv.y;
            acc.z += wj * xv.z; acc.w += wj * xv.w;
        }
    } else {
        for (int c = 0; c < cnt; c += SMAX) {
            const int cn = (cnt - c < SMAX) ? (cnt - c) : SMAX;
            if (tid < cn) {
                const float4 e = reinterpret_cast<const float4*>(g_scores)[lo + c + tid];
                const float a0 = e.x * i0, a1 = e.y * i1, a2 = e.z * i2, a3 = e.w * i3;
                attn[lo + c + tid]                  = a0;
                attn[(size_t)N + lo + c + tid]      = a1;
                attn[(size_t)2 * N + lo + c + tid]  = a2;
                attn[(size_t)3 * N + lo + c + tid]  = a3;
                s_w[tid] = 0.25f * (a0 + a1 + a2 + a3);
            }
            __syncthreads();
            for (int j = warp; j < cn; j += NWARPS) {
                const float wj  = s_w[j];
                const float4 xv = x4[(size_t)(lo + c + j) * 32 + lane];
                acc.x += wj * xv.x; acc.y += wj * xv.y;
                acc.z += wj * xv.z; acc.w += wj * xv.w;
            }
            __syncthreads();
        }
    }

    // cross-warp combine: 8 partial float4 per column group
    reinterpret_cast<float4*>(s_part)[warp * 32 + lane] = acc;
    __syncthreads();
    if (tid < DD) {
        float r = 0.f;
        #pragma unroll
        for (int w = 0; w < NWARPS; w++) r += s_part[w * DD + tid];
        pooled[(size_t)b * DD + tid] = r;
    }
}

extern "C" void kernel_launch(void* const* d_in, const int* in_sizes, int n_in,
                              void* d_out, int out_size)
{
    const float* x    = (const float*)d_in[0];
    const int*   ids  = (const int*)  d_in[1];
    const float* W    = (const float*)d_in[2];
    const float* bias = (const float*)d_in[3];
    const float* temp = (const float*)d_in[4];

    const int N = in_sizes[0] / DD;          // x is [N, 128]
    const int B = (out_size - HH * N) / DD;  // out = [B*D pooled | H*N attn]

    float* pooled = (float*)d_out;
    float* attn   = (float*)d_out + (size_t)B * DD;

    int blocks0 = (N + 255) / 256;
    if (blocks0 > 2048) blocks0 = 2048;
    seg_offsets_kernel<<<blocks0, 256>>>(ids, N, B);
    mhap_kernel<<<B, NTHREADS>>>(x, W, bias, temp, pooled, attn, N);
    (void)n_in;
}